// round 11
// baseline (speedup 1.0000x reference)
#include <cuda_runtime.h>
#include <cuda_fp16.h>
#include <math.h>
#include <stdint.h>

#define SLEN 4096
#define DMODEL 1024
#define NHEAD 16
#define HDIM 64

// ---------------------------------------------------------------------------
// scratch (allocation-free rule: __device__ globals)
// ---------------------------------------------------------------------------
__device__ __half g_xh[SLEN * DMODEL], g_xl[SLEN * DMODEL];
__device__ __half g_wqh[DMODEL * DMODEL], g_wql[DMODEL * DMODEL];
__device__ __half g_wkh[DMODEL * DMODEL], g_wkl[DMODEL * DMODEL];
__device__ __half g_wvh[DMODEL * DMODEL], g_wvl[DMODEL * DMODEL];
__device__ __half g_woh[DMODEL * DMODEL], g_wol[DMODEL * DMODEL];
__device__ __half g_qh[SLEN * DMODEL], g_ql[SLEN * DMODEL];
__device__ __half g_kh[SLEN * DMODEL], g_kl[SLEN * DMODEL];
__device__ __half g_vh[SLEN * DMODEL];
__device__ __half g_oh[SLEN * DMODEL], g_ol[SLEN * DMODEL];

// ---------------------------------------------------------------------------
// helpers
// ---------------------------------------------------------------------------
__device__ __forceinline__ void mma_f16(
    float c[4], uint32_t a0, uint32_t a1, uint32_t a2, uint32_t a3,
    uint32_t b0, uint32_t b1)
{
    asm volatile(
        "mma.sync.aligned.m16n8k16.row.col.f32.f16.f16.f32 "
        "{%0,%1,%2,%3},{%4,%5,%6,%7},{%8,%9},{%0,%1,%2,%3};\n"
        : "+f"(c[0]), "+f"(c[1]), "+f"(c[2]), "+f"(c[3])
        : "r"(a0), "r"(a1), "r"(a2), "r"(a3), "r"(b0), "r"(b1));
}

__device__ __forceinline__ void cp_async16(uint32_t smem_addr, const void* gptr) {
    asm volatile("cp.async.ca.shared.global [%0], [%1], 16;\n"
                 :: "r"(smem_addr), "l"(gptr));
}
__device__ __forceinline__ void cp_commit() {
    asm volatile("cp.async.commit_group;\n" ::: "memory");
}
__device__ __forceinline__ void cp_wait0() {
    asm volatile("cp.async.wait_group 0;\n" ::: "memory");
}

// ---------------------------------------------------------------------------
// pre-pass: split fp32 array into hi/lo fp16 arrays (n % 4 == 0)
// ---------------------------------------------------------------------------
__global__ __launch_bounds__(256) void split_f32(
    const float* __restrict__ src, __half* __restrict__ hi,
    __half* __restrict__ lo, int n)
{
    int i = (blockIdx.x * 256 + threadIdx.x) * 4;
    if (i >= n) return;
    float4 v = *(const float4*)(src + i);
    __half h0 = __float2half_rn(v.x), h1 = __float2half_rn(v.y);
    __half h2 = __float2half_rn(v.z), h3 = __float2half_rn(v.w);
    __half l0 = __float2half_rn(v.x - __half2float(h0));
    __half l1 = __float2half_rn(v.y - __half2float(h1));
    __half l2 = __float2half_rn(v.z - __half2float(h2));
    __half l3 = __float2half_rn(v.w - __half2float(h3));
    __half2 ha = __halves2half2(h0, h1), hb = __halves2half2(h2, h3);
    __half2 la = __halves2half2(l0, l1), lb = __halves2half2(l2, l3);
    uint2 hp = make_uint2(*(uint32_t*)&ha, *(uint32_t*)&hb);
    uint2 lp = make_uint2(*(uint32_t*)&la, *(uint32_t*)&lb);
    *(uint2*)(hi + i) = hp;
    *(uint2*)(lo + i) = lp;
}

// ---------------------------------------------------------------------------
// C[M][N] = A[M][K] @ B[N][K]^T + bias[N] via 3xFP16 mma (pre-split inputs).
// ---------------------------------------------------------------------------
#define BM 128
#define BN 128
#define GS 12

__global__ __launch_bounds__(256) void gemm_f16x3_hh(
    const __half* __restrict__ Ah, const __half* __restrict__ Al,
    const __half* __restrict__ Bh, const __half* __restrict__ Bl,
    const float* __restrict__ bias,
    float* __restrict__ Cf, __half* __restrict__ Ch, __half* __restrict__ Cl,
    int M, int N, int K)
{
    __shared__ uint32_t AsH[2][BM][GS];
    __shared__ uint32_t AsL[2][BM][GS];
    __shared__ uint32_t BsH[2][BN][GS];
    __shared__ uint32_t BsL[2][BN][GS];

    const int tid  = threadIdx.x;
    const int warp = tid >> 5;
    const int lane = tid & 31;
    const int wm = warp >> 2;
    const int wn = warp & 3;
    const int lr = lane >> 2;
    const int qd = lane & 3;
    const int brow = blockIdx.y * BM;
    const int bcol = blockIdx.x * BN;

    float acc[4][4][4];
#pragma unroll
    for (int i = 0; i < 4; i++)
#pragma unroll
        for (int j = 0; j < 4; j++)
#pragma unroll
            for (int f = 0; f < 4; f++) acc[i][j][f] = 0.f;

    const int NKB = K / 16;
    const int lrow = tid >> 1;
    const int lpart = tid & 1;

    auto load_tile = [&](int kb, int buf) {
        size_t ga = (size_t)(brow + lrow) * K + kb * 16 + lpart * 8;
        size_t gb = (size_t)(bcol + lrow) * K + kb * 16 + lpart * 8;
        *(uint4*)&AsH[buf][lrow][lpart * 4] = *(const uint4*)&Ah[ga];
        *(uint4*)&AsL[buf][lrow][lpart * 4] = *(const uint4*)&Al[ga];
        *(uint4*)&BsH[buf][lrow][lpart * 4] = *(const uint4*)&Bh[gb];
        *(uint4*)&BsL[buf][lrow][lpart * 4] = *(const uint4*)&Bl[gb];
    };

    load_tile(0, 0);
    __syncthreads();

    for (int kb = 0; kb < NKB; kb++) {
        const int buf = kb & 1;
        if (kb + 1 < NKB) load_tile(kb + 1, buf ^ 1);

        uint32_t ah[4][4], al[4][4];
#pragma unroll
        for (int mt = 0; mt < 4; mt++) {
            int r = wm * 64 + mt * 16 + lr;
            ah[mt][0] = AsH[buf][r    ][qd];
            ah[mt][1] = AsH[buf][r + 8][qd];
            ah[mt][2] = AsH[buf][r    ][qd + 4];
            ah[mt][3] = AsH[buf][r + 8][qd + 4];
            al[mt][0] = AsL[buf][r    ][qd];
            al[mt][1] = AsL[buf][r + 8][qd];
            al[mt][2] = AsL[buf][r    ][qd + 4];
            al[mt][3] = AsL[buf][r + 8][qd + 4];
        }
#pragma unroll
        for (int nt = 0; nt < 4; nt++) {
            int c = wn * 32 + nt * 8 + lr;
            uint32_t bh0 = BsH[buf][c][qd], bh1 = BsH[buf][c][qd + 4];
            uint32_t bl0 = BsL[buf][c][qd], bl1 = BsL[buf][c][qd + 4];
#pragma unroll
            for (int mt = 0; mt < 4; mt++) {
                mma_f16(acc[mt][nt], ah[mt][0], ah[mt][1], ah[mt][2], ah[mt][3], bh0, bh1);
                mma_f16(acc[mt][nt], ah[mt][0], ah[mt][1], ah[mt][2], ah[mt][3], bl0, bl1);
                mma_f16(acc[mt][nt], al[mt][0], al[mt][1], al[mt][2], al[mt][3], bh0, bh1);
            }
        }
        __syncthreads();
    }

#pragma unroll
    for (int mt = 0; mt < 4; mt++) {
        int r0 = brow + wm * 64 + mt * 16 + lr;
#pragma unroll
        for (int nt = 0; nt < 4; nt++) {
            int col = bcol + wn * 32 + nt * 8 + 2 * qd;
            float b0 = bias ? bias[col]     : 0.f;
            float b1 = bias ? bias[col + 1] : 0.f;
            float v00 = acc[mt][nt][0] + b0, v01 = acc[mt][nt][1] + b1;
            float v10 = acc[mt][nt][2] + b0, v11 = acc[mt][nt][3] + b1;
            if (Cf) {
                *(float2*)&Cf[(size_t)r0 * N + col]       = make_float2(v00, v01);
                *(float2*)&Cf[(size_t)(r0 + 8) * N + col] = make_float2(v10, v11);
            } else {
                __half h00 = __float2half_rn(v00), h01 = __float2half_rn(v01);
                __half h10 = __float2half_rn(v10), h11 = __float2half_rn(v11);
                *(__half2*)&Ch[(size_t)r0 * N + col]       = __halves2half2(h00, h01);
                *(__half2*)&Ch[(size_t)(r0 + 8) * N + col] = __halves2half2(h10, h11);
                if (Cl) {
                    __half q00 = __float2half_rn(v00 - __half2float(h00));
                    __half q01 = __float2half_rn(v01 - __half2float(h01));
                    __half q10 = __float2half_rn(v10 - __half2float(h10));
                    __half q11 = __float2half_rn(v11 - __half2float(h11));
                    *(__half2*)&Cl[(size_t)r0 * N + col]       = __halves2half2(q00, q01);
                    *(__half2*)&Cl[(size_t)(r0 + 8) * N + col] = __halves2half2(q10, q11);
                }
            }
        }
    }
}

// ---------------------------------------------------------------------------
// Tensor-core causal flash attention with ALiBi (all-fp16 mma, pre-split io).
// BQ=64 = 4 warps x m16, 128 threads, BT=32, balanced q-tile pairs.
// Q fragments loaded DIRECTLY from gmem (no smem staging); K via cp.async;
// smem 28.7KB + <=102 regs -> 5 CTAs/SM.
// ---------------------------------------------------------------------------
#define BQ 64
#define BT 32
#define QS 36
#define VPAD 8
#define ATHREADS 128
#define NQT (SLEN / BQ)       // 64

__global__ __launch_bounds__(ATHREADS, 5) void flash_attn_f16(
    const __half* __restrict__ Qh, const __half* __restrict__ Ql,
    const __half* __restrict__ Kh, const __half* __restrict__ Kl,
    const __half* __restrict__ Vh,
    __half* __restrict__ Oh, __half* __restrict__ Ol)
{
    const int h = blockIdx.y;

    const int tid  = threadIdx.x;
    const int warp = tid >> 5;
    const int lane = tid & 31;
    const int lr   = lane >> 2;
    const int qd   = lane & 3;
    const int R    = warp * 16;
    const int hd   = h * HDIM;

    __shared__ uint32_t Kh2[2][BT][QS];          // 9216 B
    __shared__ uint32_t Kl2[2][BT][QS];          // 9216 B
    __shared__ __half   VsT[2][HDIM][BT + VPAD]; // 10240 B  (total 28672 B)

    const float LOG2E = 1.4426950408889634f;
    const float sc2 = 0.125f * LOG2E;
    const float sl2 = exp2f(-0.5f * (float)(h + 1)) * LOG2E;

    auto load_kv = [&](int t, int buf) {
        const int t0 = t * BT;
        // K tiles: async 16B copies, no register round-trip
#pragma unroll
        for (int it = 0; it < 2; it++) {
            int f = tid + it * ATHREADS;        // 0..255
            int r = f >> 3, part = f & 7;       // 32 rows x 8 parts (8 halves)
            size_t g = (size_t)(t0 + r) * DMODEL + hd + part * 8;
            uint32_t dh = (uint32_t)__cvta_generic_to_shared(&Kh2[buf][r][part * 4]);
            uint32_t dl = (uint32_t)__cvta_generic_to_shared(&Kl2[buf][r][part * 4]);
            cp_async16(dh, &Kh[g]);
            cp_async16(dl, &Kl[g]);
        }
        // V transpose (synchronous, small)
#pragma unroll
        for (int it = 0; it < 2; it++) {
            int f = tid + it * ATHREADS;        // 0..255
            int dv4 = (f & 15) * 4;             // head-dim group of 4
            int tp  = f >> 4;                   // time pair 0..15
            size_t g0 = (size_t)(t0 + 2 * tp) * DMODEL + hd + dv4;
            uint2 va = *(const uint2*)&Vh[g0];
            uint2 vb = *(const uint2*)&Vh[g0 + DMODEL];
            __half2 a01 = *(__half2*)&va.x, a23 = *(__half2*)&va.y;
            __half2 b01 = *(__half2*)&vb.x, b23 = *(__half2*)&vb.y;
            *(__half2*)&VsT[buf][dv4 + 0][2 * tp] = __halves2half2(__low2half(a01),  __low2half(b01));
            *(__half2*)&VsT[buf][dv4 + 1][2 * tp] = __halves2half2(__high2half(a01), __high2half(b01));
            *(__half2*)&VsT[buf][dv4 + 2][2 * tp] = __halves2half2(__low2half(a23),  __low2half(b23));
            *(__half2*)&VsT[buf][dv4 + 3][2 * tp] = __halves2half2(__high2half(a23), __high2half(b23));
        }
        cp_commit();
    };

#pragma unroll 1
    for (int rep = 0; rep < 2; rep++) {
        const int qt = (rep == 0) ? (int)blockIdx.x : (NQT - 1 - (int)blockIdx.x);
        const int q0 = qt * BQ;

        const int gr0 = q0 + R + lr;
        const int gr1 = gr0 + 8;

        // ---- Q fragments (hi and lo) straight from gmem ----
        uint32_t qh[4][4], ql[4][4];
#pragma unroll
        for (int kt = 0; kt < 4; kt++) {
            int c0 = kt * 8 + qd;                            // uint32-pair index
            size_t b0 = (size_t)gr0 * DMODEL + hd + 2 * c0;  // half index
            size_t b1 = (size_t)gr1 * DMODEL + hd + 2 * c0;
            qh[kt][0] = *(const uint32_t*)&Qh[b0];
            qh[kt][1] = *(const uint32_t*)&Qh[b1];
            qh[kt][2] = *(const uint32_t*)&Qh[b0 + 8];
            qh[kt][3] = *(const uint32_t*)&Qh[b1 + 8];
            ql[kt][0] = *(const uint32_t*)&Ql[b0];
            ql[kt][1] = *(const uint32_t*)&Ql[b1];
            ql[kt][2] = *(const uint32_t*)&Ql[b0 + 8];
            ql[kt][3] = *(const uint32_t*)&Ql[b1 + 8];
        }

        load_kv(0, 0);
        cp_wait0();
        __syncthreads();

        float oacc[8][4];
#pragma unroll
        for (int i = 0; i < 8; i++)
#pragma unroll
            for (int j = 0; j < 4; j++) oacc[i][j] = 0.f;
        float m0 = -INFINITY, m1 = -INFINITY, l0 = 0.f, l1 = 0.f;

        const int ntiles = 2 * (qt + 1);
        for (int t = 0; t < ntiles; t++) {
            const int buf = t & 1;
            const int t0 = t * BT;
            if (t + 1 < ntiles) load_kv(t + 1, buf ^ 1);

            // ---- S = Q K^T (3xFP16, k16) ----
            float sa[4][4];
#pragma unroll
            for (int nt = 0; nt < 4; nt++)
#pragma unroll
                for (int f = 0; f < 4; f++) sa[nt][f] = 0.f;

#pragma unroll
            for (int kt = 0; kt < 4; kt++) {
                int c0 = kt * 8 + qd;
#pragma unroll
                for (int nt = 0; nt < 4; nt++) {
                    int tr_ = nt * 8 + lr;
                    uint32_t bh0 = Kh2[buf][tr_][c0], bh1 = Kh2[buf][tr_][c0 + 4];
                    uint32_t bl0 = Kl2[buf][tr_][c0], bl1 = Kl2[buf][tr_][c0 + 4];
                    mma_f16(sa[nt], qh[kt][0], qh[kt][1], qh[kt][2], qh[kt][3], bh0, bh1);
                    mma_f16(sa[nt], qh[kt][0], qh[kt][1], qh[kt][2], qh[kt][3], bl0, bl1);
                    mma_f16(sa[nt], ql[kt][0], ql[kt][1], ql[kt][2], ql[kt][3], bh0, bh1);
                }
            }

            // ---- bias + causal mask + online softmax (base-2) ----
            float mx0 = -INFINITY, mx1 = -INFINITY;
#pragma unroll
            for (int nt = 0; nt < 4; nt++) {
                int c = t0 + nt * 8 + 2 * qd;
                float x00 = sa[nt][0] * sc2 - sl2 * (float)c;
                float x01 = sa[nt][1] * sc2 - sl2 * (float)(c + 1);
                float x10 = sa[nt][2] * sc2 - sl2 * (float)c;
                float x11 = sa[nt][3] * sc2 - sl2 * (float)(c + 1);
                if (c     > gr0) x00 = -INFINITY;
                if (c + 1 > gr0) x01 = -INFINITY;
                if (c     > gr1) x10 = -INFINITY;
                if (c + 1 > gr1) x11 = -INFINITY;
                sa[nt][0] = x00; sa[nt][1] = x01; sa[nt][2] = x10; sa[nt][3] = x11;
                mx0 = fmaxf(mx0, fmaxf(x00, x01));
                mx1 = fmaxf(mx1, fmaxf(x10, x11));
            }
            mx0 = fmaxf(mx0, __shfl_xor_sync(0xffffffffu, mx0, 1));
            mx0 = fmaxf(mx0, __shfl_xor_sync(0xffffffffu, mx0, 2));
            mx1 = fmaxf(mx1, __shfl_xor_sync(0xffffffffu, mx1, 1));
            mx1 = fmaxf(mx1, __shfl_xor_sync(0xffffffffu, mx1, 2));

            float nm0 = fmaxf(m0, mx0), nm1 = fmaxf(m1, mx1);
            float s0 = exp2f(m0 - nm0), s1 = exp2f(m1 - nm1);
            m0 = nm0; m1 = nm1;

            float rs0 = 0.f, rs1 = 0.f;
            uint32_t pa[2][4];
#pragma unroll
            for (int nt = 0; nt < 4; nt++) {
                float p00 = exp2f(sa[nt][0] - m0);
                float p01 = exp2f(sa[nt][1] - m0);
                float p10 = exp2f(sa[nt][2] - m1);
                float p11 = exp2f(sa[nt][3] - m1);
                rs0 += p00 + p01;
                rs1 += p10 + p11;
                __half2 h0 = __floats2half2_rn(p00, p01);
                __half2 h1 = __floats2half2_rn(p10, p11);
                pa[nt >> 1][(nt & 1) * 2 + 0] = *(uint32_t*)&h0;
                pa[nt >> 1][(nt & 1) * 2 + 1] = *(uint32_t*)&h1;
            }
            rs0 += __shfl_xor_sync(0xffffffffu, rs0, 1);
            rs0 += __shfl_xor_sync(0xffffffffu, rs0, 2);
            rs1 += __shfl_xor_sync(0xffffffffu, rs1, 1);
            rs1 += __shfl_xor_sync(0xffffffffu, rs1, 2);
            l0 = l0 * s0 + rs0;
            l1 = l1 * s1 + rs1;

            // ---- rescale O, then O += P V (fp16 mma) ----
#pragma unroll
            for (int ntO = 0; ntO < 8; ntO++) {
                oacc[ntO][0] *= s0; oacc[ntO][1] *= s0;
                oacc[ntO][2] *= s1; oacc[ntO][3] *= s1;
            }
#pragma unroll
            for (int ktp = 0; ktp < 2; ktp++) {
#pragma unroll
                for (int ntO = 0; ntO < 8; ntO++) {
                    int dcol = ntO * 8 + lr;
                    uint32_t b0 = *(const uint32_t*)&VsT[buf][dcol][ktp * 16 + 2 * qd];
                    uint32_t b1 = *(const uint32_t*)&VsT[buf][dcol][ktp * 16 + 2 * qd + 8];
                    mma_f16(oacc[ntO], pa[ktp][0], pa[ktp][1], pa[ktp][2], pa[ktp][3], b0, b1);
                }
            }
            cp_wait0();            // prefetched K tile landed
            __syncthreads();
        }

        // ---- epilogue: write hi/lo halves for the output GEMM ----
        float inv0 = 1.f / l0, inv1 = 1.f / l1;
#pragma unroll
        for (int ntO = 0; ntO < 8; ntO++) {
            int col = hd + ntO * 8 + 2 * qd;
            float v00 = oacc[ntO][0] * inv0, v01 = oacc[ntO][1] * inv0;
            float v10 = oacc[ntO][2] * inv1, v11 = oacc[ntO][3] * inv1;
            __half h00 = __float2half_rn(v00), h01 = __float2half_rn(v01);
            __half h10 = __float2half_rn(v10), h11 = __float2half_rn(v11);
            *(__half2*)&Oh[(size_t)gr0 * DMODEL + col] = __halves2half2(h00, h01);
            *(__half2*)&Oh[(size_t)gr1 * DMODEL + col] = __halves2half2(h10, h11);
            __half q00 = __float2half_rn(v00 - __half2float(h00));
            __half q01 = __float2half_rn(v01 - __half2float(h01));
            __half q10 = __float2half_rn(v10 - __half2float(h10));
            __half q11 = __float2half_rn(v11 - __half2float(h11));
            *(__half2*)&Ol[(size_t)gr0 * DMODEL + col] = __halves2half2(q00, q01);
            *(__half2*)&Ol[(size_t)gr1 * DMODEL + col] = __halves2half2(q10, q11);
        }
    }
}

// ---------------------------------------------------------------------------
extern "C" void kernel_launch(void* const* d_in, const int* in_sizes, int n_in,
                              void* d_out, int out_size)
{
    const float* x  = (const float*)d_in[0];
    const float* Wq = (const float*)d_in[1];
    const float* bq = (const float*)d_in[2];
    const float* Wk = (const float*)d_in[3];
    const float* Wv = (const float*)d_in[4];
    const float* bv = (const float*)d_in[5];
    const float* Wo = (const float*)d_in[6];
    float* out = (float*)d_out;

    __half *xh, *xl, *wqh, *wql, *wkh, *wkl, *wvh, *wvl, *woh, *wol;
    __half *qh, *ql, *kh, *kl, *vh, *oh, *ol;
    cudaGetSymbolAddress((void**)&xh, g_xh);   cudaGetSymbolAddress((void**)&xl, g_xl);
    cudaGetSymbolAddress((void**)&wqh, g_wqh); cudaGetSymbolAddress((void**)&wql, g_wql);
    cudaGetSymbolAddress((void**)&wkh, g_wkh); cudaGetSymbolAddress((void**)&wkl, g_wkl);
    cudaGetSymbolAddress((void**)&wvh, g_wvh); cudaGetSymbolAddress((void**)&wvl, g_wvl);
    cudaGetSymbolAddress((void**)&woh, g_woh); cudaGetSymbolAddress((void**)&wol, g_wol);
    cudaGetSymbolAddress((void**)&qh, g_qh);   cudaGetSymbolAddress((void**)&ql, g_ql);
    cudaGetSymbolAddress((void**)&kh, g_kh);   cudaGetSymbolAddress((void**)&kl, g_kl);
    cudaGetSymbolAddress((void**)&vh, g_vh);
    cudaGetSymbolAddress((void**)&oh, g_oh);   cudaGetSymbolAddress((void**)&ol, g_ol);

    const int NX = SLEN * DMODEL;      // 4M
    const int NW = DMODEL * DMODEL;    // 1M
    split_f32<<<NX / 1024, 256>>>(x,  xh,  xl,  NX);
    split_f32<<<NW / 1024, 256>>>(Wq, wqh, wql, NW);
    split_f32<<<NW / 1024, 256>>>(Wk, wkh, wkl, NW);
    split_f32<<<NW / 1024, 256>>>(Wv, wvh, wvl, NW);
    split_f32<<<NW / 1024, 256>>>(Wo, woh, wol, NW);

    dim3 ggrid(DMODEL / BN, SLEN / BM);   // (8, 32)
    gemm_f16x3_hh<<<ggrid, 256>>>(xh, xl, wqh, wql, bq,
                                  nullptr, qh, ql, SLEN, DMODEL, DMODEL);
    gemm_f16x3_hh<<<ggrid, 256>>>(xh, xl, wkh, wkl, nullptr,
                                  nullptr, kh, kl, SLEN, DMODEL, DMODEL);
    gemm_f16x3_hh<<<ggrid, 256>>>(xh, xl, wvh, wvl, bv,
                                  nullptr, vh, nullptr, SLEN, DMODEL, DMODEL);

    dim3 agrid(NQT / 2, NHEAD);           // (32, 16) balanced pairs
    flash_attn_f16<<<agrid, ATHREADS>>>(qh, ql, kh, kl, vh, oh, ol);

    gemm_f16x3_hh<<<ggrid, 256>>>(oh, ol, woh, wol, nullptr,
                                  out, nullptr, nullptr, SLEN, DMODEL, DMODEL);
}

// round 13
// speedup vs baseline: 1.0903x; 1.0903x over previous
#include <cuda_runtime.h>
#include <cuda_fp16.h>
#include <math.h>
#include <stdint.h>

#define SLEN 4096
#define DMODEL 1024
#define NHEAD 16
#define HDIM 64

// ---------------------------------------------------------------------------
// scratch (allocation-free rule: __device__ globals)
// ---------------------------------------------------------------------------
__device__ __half g_xh[SLEN * DMODEL], g_xl[SLEN * DMODEL];
__device__ __half g_wqh[DMODEL * DMODEL], g_wql[DMODEL * DMODEL];
__device__ __half g_wkh[DMODEL * DMODEL], g_wkl[DMODEL * DMODEL];
__device__ __half g_wvh[DMODEL * DMODEL], g_wvl[DMODEL * DMODEL];
__device__ __half g_woh[DMODEL * DMODEL], g_wol[DMODEL * DMODEL];
__device__ __half g_qh[SLEN * DMODEL], g_ql[SLEN * DMODEL];
__device__ __half g_kh[SLEN * DMODEL], g_kl[SLEN * DMODEL];
__device__ __half g_vh[SLEN * DMODEL];
__device__ __half g_vt[DMODEL * SLEN];           // V transposed [d][s]
__device__ __half g_oh[SLEN * DMODEL], g_ol[SLEN * DMODEL];

// ---------------------------------------------------------------------------
// helpers
// ---------------------------------------------------------------------------
__device__ __forceinline__ void mma_f16(
    float c[4], uint32_t a0, uint32_t a1, uint32_t a2, uint32_t a3,
    uint32_t b0, uint32_t b1)
{
    asm volatile(
        "mma.sync.aligned.m16n8k16.row.col.f32.f16.f16.f32 "
        "{%0,%1,%2,%3},{%4,%5,%6,%7},{%8,%9},{%0,%1,%2,%3};\n"
        : "+f"(c[0]), "+f"(c[1]), "+f"(c[2]), "+f"(c[3])
        : "r"(a0), "r"(a1), "r"(a2), "r"(a3), "r"(b0), "r"(b1));
}

__device__ __forceinline__ void cp_async16(uint32_t smem_addr, const void* gptr) {
    asm volatile("cp.async.ca.shared.global [%0], [%1], 16;\n"
                 :: "r"(smem_addr), "l"(gptr));
}
__device__ __forceinline__ void cp_commit() {
    asm volatile("cp.async.commit_group;\n" ::: "memory");
}
__device__ __forceinline__ void cp_wait0() {
    asm volatile("cp.async.wait_group 0;\n" ::: "memory");
}

// ---------------------------------------------------------------------------
// pre-pass: split fp32 array into hi/lo fp16 arrays (n % 4 == 0)
// ---------------------------------------------------------------------------
__global__ __launch_bounds__(256) void split_f32(
    const float* __restrict__ src, __half* __restrict__ hi,
    __half* __restrict__ lo, int n)
{
    int i = (blockIdx.x * 256 + threadIdx.x) * 4;
    if (i >= n) return;
    float4 v = *(const float4*)(src + i);
    __half h0 = __float2half_rn(v.x), h1 = __float2half_rn(v.y);
    __half h2 = __float2half_rn(v.z), h3 = __float2half_rn(v.w);
    __half l0 = __float2half_rn(v.x - __half2float(h0));
    __half l1 = __float2half_rn(v.y - __half2float(h1));
    __half l2 = __float2half_rn(v.z - __half2float(h2));
    __half l3 = __float2half_rn(v.w - __half2float(h3));
    __half2 ha = __halves2half2(h0, h1), hb = __halves2half2(h2, h3);
    __half2 la = __halves2half2(l0, l1), lb = __halves2half2(l2, l3);
    uint2 hp = make_uint2(*(uint32_t*)&ha, *(uint32_t*)&hb);
    uint2 lp = make_uint2(*(uint32_t*)&la, *(uint32_t*)&lb);
    *(uint2*)(hi + i) = hp;
    *(uint2*)(lo + i) = lp;
}

// ---------------------------------------------------------------------------
// transpose half [SLEN][DMODEL] -> [DMODEL][SLEN]
// ---------------------------------------------------------------------------
__global__ __launch_bounds__(256) void transpose_h(
    const __half* __restrict__ src, __half* __restrict__ dst)
{
    __shared__ __half tile[32][33];
    const int d0 = blockIdx.x * 32, s0 = blockIdx.y * 32;
    const int tx = threadIdx.x & 31, ty = threadIdx.x >> 5;   // 32 x 8
#pragma unroll
    for (int k = 0; k < 4; k++)
        tile[ty + 8 * k][tx] = src[(size_t)(s0 + ty + 8 * k) * DMODEL + d0 + tx];
    __syncthreads();
#pragma unroll
    for (int k = 0; k < 4; k++)
        dst[(size_t)(d0 + ty + 8 * k) * SLEN + s0 + tx] = tile[tx][ty + 8 * k];
}

// ---------------------------------------------------------------------------
// C[M][N] = A[M][K] @ B[N][K]^T + bias[N] via 3xFP16 mma (pre-split inputs).
// Loaders via cp.async; double-buffered smem.
// ---------------------------------------------------------------------------
#define BM 128
#define BN 128
#define GS 12

__global__ __launch_bounds__(256) void gemm_f16x3_hh(
    const __half* __restrict__ Ah, const __half* __restrict__ Al,
    const __half* __restrict__ Bh, const __half* __restrict__ Bl,
    const float* __restrict__ bias,
    float* __restrict__ Cf, __half* __restrict__ Ch, __half* __restrict__ Cl,
    int M, int N, int K)
{
    __shared__ uint32_t AsH[2][BM][GS];
    __shared__ uint32_t AsL[2][BM][GS];
    __shared__ uint32_t BsH[2][BN][GS];
    __shared__ uint32_t BsL[2][BN][GS];

    const int tid  = threadIdx.x;
    const int warp = tid >> 5;
    const int lane = tid & 31;
    const int wm = warp >> 2;
    const int wn = warp & 3;
    const int lr = lane >> 2;
    const int qd = lane & 3;
    const int brow = blockIdx.y * BM;
    const int bcol = blockIdx.x * BN;

    float acc[4][4][4];
#pragma unroll
    for (int i = 0; i < 4; i++)
#pragma unroll
        for (int j = 0; j < 4; j++)
#pragma unroll
            for (int f = 0; f < 4; f++) acc[i][j][f] = 0.f;

    const int NKB = K / 16;
    const int lrow = tid >> 1;
    const int lpart = tid & 1;

    auto load_tile = [&](int kb, int buf) {
        size_t ga = (size_t)(brow + lrow) * K + kb * 16 + lpart * 8;
        size_t gb = (size_t)(bcol + lrow) * K + kb * 16 + lpart * 8;
        cp_async16((uint32_t)__cvta_generic_to_shared(&AsH[buf][lrow][lpart * 4]), &Ah[ga]);
        cp_async16((uint32_t)__cvta_generic_to_shared(&AsL[buf][lrow][lpart * 4]), &Al[ga]);
        cp_async16((uint32_t)__cvta_generic_to_shared(&BsH[buf][lrow][lpart * 4]), &Bh[gb]);
        cp_async16((uint32_t)__cvta_generic_to_shared(&BsL[buf][lrow][lpart * 4]), &Bl[gb]);
        cp_commit();
    };

    load_tile(0, 0);
    cp_wait0();
    __syncthreads();

    for (int kb = 0; kb < NKB; kb++) {
        const int buf = kb & 1;
        if (kb + 1 < NKB) load_tile(kb + 1, buf ^ 1);

        uint32_t ah[4][4], al[4][4];
#pragma unroll
        for (int mt = 0; mt < 4; mt++) {
            int r = wm * 64 + mt * 16 + lr;
            ah[mt][0] = AsH[buf][r    ][qd];
            ah[mt][1] = AsH[buf][r + 8][qd];
            ah[mt][2] = AsH[buf][r    ][qd + 4];
            ah[mt][3] = AsH[buf][r + 8][qd + 4];
            al[mt][0] = AsL[buf][r    ][qd];
            al[mt][1] = AsL[buf][r + 8][qd];
            al[mt][2] = AsL[buf][r    ][qd + 4];
            al[mt][3] = AsL[buf][r + 8][qd + 4];
        }
#pragma unroll
        for (int nt = 0; nt < 4; nt++) {
            int c = wn * 32 + nt * 8 + lr;
            uint32_t bh0 = BsH[buf][c][qd], bh1 = BsH[buf][c][qd + 4];
            uint32_t bl0 = BsL[buf][c][qd], bl1 = BsL[buf][c][qd + 4];
#pragma unroll
            for (int mt = 0; mt < 4; mt++) {
                mma_f16(acc[mt][nt], ah[mt][0], ah[mt][1], ah[mt][2], ah[mt][3], bh0, bh1);
                mma_f16(acc[mt][nt], ah[mt][0], ah[mt][1], ah[mt][2], ah[mt][3], bl0, bl1);
                mma_f16(acc[mt][nt], al[mt][0], al[mt][1], al[mt][2], al[mt][3], bh0, bh1);
            }
        }
        cp_wait0();
        __syncthreads();
    }

#pragma unroll
    for (int mt = 0; mt < 4; mt++) {
        int r0 = brow + wm * 64 + mt * 16 + lr;
#pragma unroll
        for (int nt = 0; nt < 4; nt++) {
            int col = bcol + wn * 32 + nt * 8 + 2 * qd;
            float b0 = bias ? bias[col]     : 0.f;
            float b1 = bias ? bias[col + 1] : 0.f;
            float v00 = acc[mt][nt][0] + b0, v01 = acc[mt][nt][1] + b1;
            float v10 = acc[mt][nt][2] + b0, v11 = acc[mt][nt][3] + b1;
            if (Cf) {
                *(float2*)&Cf[(size_t)r0 * N + col]       = make_float2(v00, v01);
                *(float2*)&Cf[(size_t)(r0 + 8) * N + col] = make_float2(v10, v11);
            } else {
                __half h00 = __float2half_rn(v00), h01 = __float2half_rn(v01);
                __half h10 = __float2half_rn(v10), h11 = __float2half_rn(v11);
                *(__half2*)&Ch[(size_t)r0 * N + col]       = __halves2half2(h00, h01);
                *(__half2*)&Ch[(size_t)(r0 + 8) * N + col] = __halves2half2(h10, h11);
                if (Cl) {
                    __half q00 = __float2half_rn(v00 - __half2float(h00));
                    __half q01 = __float2half_rn(v01 - __half2float(h01));
                    __half q10 = __float2half_rn(v10 - __half2float(h10));
                    __half q11 = __float2half_rn(v11 - __half2float(h11));
                    *(__half2*)&Cl[(size_t)r0 * N + col]       = __halves2half2(q00, q01);
                    *(__half2*)&Cl[(size_t)(r0 + 8) * N + col] = __halves2half2(q10, q11);
                }
            }
        }
    }
}

// ---------------------------------------------------------------------------
// Tensor-core causal flash attention with ALiBi (all-fp16 mma).
// All tile loads (K hi/lo, V^T) are pure cp.async 16B chunks; V pre-transposed.
// BQ=64 = 4 warps x m16, 128 threads, BT=32, balanced q-tile pairs.
// smem 28.7KB, regs capped 102 -> 5 CTAs/SM.
// ---------------------------------------------------------------------------
#define BQ 64
#define BT 32
#define QS 36
#define VROW 40        // halves per VsT row (32 data + 8 pad, 80B = 16B-mult)
#define ATHREADS 128
#define NQT (SLEN / BQ)       // 64

__global__ __launch_bounds__(ATHREADS, 5) void flash_attn_f16(
    const __half* __restrict__ Qh, const __half* __restrict__ Ql,
    const __half* __restrict__ Kh, const __half* __restrict__ Kl,
    const __half* __restrict__ Vt,
    __half* __restrict__ Oh, __half* __restrict__ Ol)
{
    const int h = blockIdx.y;

    const int tid  = threadIdx.x;
    const int warp = tid >> 5;
    const int lane = tid & 31;
    const int lr   = lane >> 2;
    const int qd   = lane & 3;
    const int R    = warp * 16;
    const int hd   = h * HDIM;

    __shared__ uint32_t Kh2[2][BT][QS];          // 9216 B
    __shared__ uint32_t Kl2[2][BT][QS];          // 9216 B
    __shared__ __half   VsT[2][HDIM][VROW];      // 10240 B  (total 28672 B)

    const float LOG2E = 1.4426950408889634f;
    const float sc2 = 0.125f * LOG2E;
    const float sl2 = exp2f(-0.5f * (float)(h + 1)) * LOG2E;

    auto load_kv = [&](int t, int buf) {
        const int t0 = t * BT;
        // K hi/lo: 32 rows x 128B each = 8 chunks/row, 2 per thread per array
#pragma unroll
        for (int it = 0; it < 2; it++) {
            int f = tid + it * ATHREADS;        // 0..255
            int r = f >> 3, part = f & 7;
            size_t g = (size_t)(t0 + r) * DMODEL + hd + part * 8;
            cp_async16((uint32_t)__cvta_generic_to_shared(&Kh2[buf][r][part * 4]), &Kh[g]);
            cp_async16((uint32_t)__cvta_generic_to_shared(&Kl2[buf][r][part * 4]), &Kl[g]);
        }
        // V^T: 64 rows x 64B each = 4 chunks/row, 2 per thread
#pragma unroll
        for (int it = 0; it < 2; it++) {
            int f = tid + it * ATHREADS;        // 0..255
            int d = f >> 2, c = f & 3;
            size_t g = (size_t)(hd + d) * SLEN + t0 + c * 8;
            cp_async16((uint32_t)__cvta_generic_to_shared(&VsT[buf][d][c * 8]), &Vt[g]);
        }
        cp_commit();
    };

#pragma unroll 1
    for (int rep = 0; rep < 2; rep++) {
        const int qt = (rep == 0) ? (int)blockIdx.x : (NQT - 1 - (int)blockIdx.x);
        const int q0 = qt * BQ;

        const int gr0 = q0 + R + lr;
        const int gr1 = gr0 + 8;

        load_kv(0, 0);

        // ---- Q fragments (hi and lo) straight from gmem (overlaps cp.async) --
        uint32_t qh[4][4], ql[4][4];
#pragma unroll
        for (int kt = 0; kt < 4; kt++) {
            int c0 = kt * 8 + qd;
            size_t b0 = (size_t)gr0 * DMODEL + hd + 2 * c0;
            size_t b1 = (size_t)gr1 * DMODEL + hd + 2 * c0;
            qh[kt][0] = *(const uint32_t*)&Qh[b0];
            qh[kt][1] = *(const uint32_t*)&Qh[b1];
            qh[kt][2] = *(const uint32_t*)&Qh[b0 + 8];
            qh[kt][3] = *(const uint32_t*)&Qh[b1 + 8];
            ql[kt][0] = *(const uint32_t*)&Ql[b0];
            ql[kt][1] = *(const uint32_t*)&Ql[b1];
            ql[kt][2] = *(const uint32_t*)&Ql[b0 + 8];
            ql[kt][3] = *(const uint32_t*)&Ql[b1 + 8];
        }

        cp_wait0();
        __syncthreads();

        float oacc[8][4];
#pragma unroll
        for (int i = 0; i < 8; i++)
#pragma unroll
            for (int j = 0; j < 4; j++) oacc[i][j] = 0.f;
        float m0 = -INFINITY, m1 = -INFINITY, l0 = 0.f, l1 = 0.f;

        const int ntiles = 2 * (qt + 1);
        for (int t = 0; t < ntiles; t++) {
            const int buf = t & 1;
            const int t0 = t * BT;
            if (t + 1 < ntiles) load_kv(t + 1, buf ^ 1);

            // ---- S = Q K^T (3xFP16, k16) ----
            float sa[4][4];
#pragma unroll
            for (int nt = 0; nt < 4; nt++)
#pragma unroll
                for (int f = 0; f < 4; f++) sa[nt][f] = 0.f;

#pragma unroll
            for (int kt = 0; kt < 4; kt++) {
                int c0 = kt * 8 + qd;
#pragma unroll
                for (int nt = 0; nt < 4; nt++) {
                    int tr_ = nt * 8 + lr;
                    uint32_t bh0 = Kh2[buf][tr_][c0], bh1 = Kh2[buf][tr_][c0 + 4];
                    uint32_t bl0 = Kl2[buf][tr_][c0], bl1 = Kl2[buf][tr_][c0 + 4];
                    mma_f16(sa[nt], qh[kt][0], qh[kt][1], qh[kt][2], qh[kt][3], bh0, bh1);
                    mma_f16(sa[nt], qh[kt][0], qh[kt][1], qh[kt][2], qh[kt][3], bl0, bl1);
                    mma_f16(sa[nt], ql[kt][0], ql[kt][1], ql[kt][2], ql[kt][3], bh0, bh1);
                }
            }

            // ---- bias + causal mask + online softmax (base-2) ----
            float mx0 = -INFINITY, mx1 = -INFINITY;
#pragma unroll
            for (int nt = 0; nt < 4; nt++) {
                int c = t0 + nt * 8 + 2 * qd;
                float x00 = sa[nt][0] * sc2 - sl2 * (float)c;
                float x01 = sa[nt][1] * sc2 - sl2 * (float)(c + 1);
                float x10 = sa[nt][2] * sc2 - sl2 * (float)c;
                float x11 = sa[nt][3] * sc2 - sl2 * (float)(c + 1);
                if (c     > gr0) x00 = -INFINITY;
                if (c + 1 > gr0) x01 = -INFINITY;
                if (c     > gr1) x10 = -INFINITY;
                if (c + 1 > gr1) x11 = -INFINITY;
                sa[nt][0] = x00; sa[nt][1] = x01; sa[nt][2] = x10; sa[nt][3] = x11;
                mx0 = fmaxf(mx0, fmaxf(x00, x01));
                mx1 = fmaxf(mx1, fmaxf(x10, x11));
            }
            mx0 = fmaxf(mx0, __shfl_xor_sync(0xffffffffu, mx0, 1));
            mx0 = fmaxf(mx0, __shfl_xor_sync(0xffffffffu, mx0, 2));
            mx1 = fmaxf(mx1, __shfl_xor_sync(0xffffffffu, mx1, 1));
            mx1 = fmaxf(mx1, __shfl_xor_sync(0xffffffffu, mx1, 2));

            float nm0 = fmaxf(m0, mx0), nm1 = fmaxf(m1, mx1);
            float s0 = exp2f(m0 - nm0), s1 = exp2f(m1 - nm1);
            m0 = nm0; m1 = nm1;

            float rs0 = 0.f, rs1 = 0.f;
            uint32_t pa[2][4];
#pragma unroll
            for (int nt = 0; nt < 4; nt++) {
                float p00 = exp2f(sa[nt][0] - m0);
                float p01 = exp2f(sa[nt][1] - m0);
                float p10 = exp2f(sa[nt][2] - m1);
                float p11 = exp2f(sa[nt][3] - m1);
                rs0 += p00 + p01;
                rs1 += p10 + p11;
                __half2 h0 = __floats2half2_rn(p00, p01);
                __half2 h1 = __floats2half2_rn(p10, p11);
                pa[nt >> 1][(nt & 1) * 2 + 0] = *(uint32_t*)&h0;
                pa[nt >> 1][(nt & 1) * 2 + 1] = *(uint32_t*)&h1;
            }
            rs0 += __shfl_xor_sync(0xffffffffu, rs0, 1);
            rs0 += __shfl_xor_sync(0xffffffffu, rs0, 2);
            rs1 += __shfl_xor_sync(0xffffffffu, rs1, 1);
            rs1 += __shfl_xor_sync(0xffffffffu, rs1, 2);
            l0 = l0 * s0 + rs0;
            l1 = l1 * s1 + rs1;

            // ---- rescale O, then O += P V (fp16 mma) ----
#pragma unroll
            for (int ntO = 0; ntO < 8; ntO++) {
                oacc[ntO][0] *= s0; oacc[ntO][1] *= s0;
                oacc[ntO][2] *= s1; oacc[ntO][3] *= s1;
            }
#pragma unroll
            for (int ktp = 0; ktp < 2; ktp++) {
#pragma unroll
                for (int ntO = 0; ntO < 8; ntO++) {
                    int dcol = ntO * 8 + lr;
                    uint32_t b0 = *(const uint32_t*)&VsT[buf][dcol][ktp * 16 + 2 * qd];
                    uint32_t b1 = *(const uint32_t*)&VsT[buf][dcol][ktp * 16 + 2 * qd + 8];
                    mma_f16(oacc[ntO], pa[ktp][0], pa[ktp][1], pa[ktp][2], pa[ktp][3], b0, b1);
                }
            }
            cp_wait0();            // prefetched t+1 landed (copied during compute)
            __syncthreads();
        }

        // ---- epilogue: write hi/lo halves for the output GEMM ----
        float inv0 = 1.f / l0, inv1 = 1.f / l1;
#pragma unroll
        for (int ntO = 0; ntO < 8; ntO++) {
            int col = hd + ntO * 8 + 2 * qd;
            float v00 = oacc[ntO][0] * inv0, v01 = oacc[ntO][1] * inv0;
            float v10 = oacc[ntO][2] * inv1, v11 = oacc[ntO][3] * inv1;
            __half h00 = __float2half_rn(v00), h01 = __float2half_rn(v01);
            __half h10 = __float2half_rn(v10), h11 = __float2half_rn(v11);
            *(__half2*)&Oh[(size_t)gr0 * DMODEL + col] = __halves2half2(h00, h01);
            *(__half2*)&Oh[(size_t)gr1 * DMODEL + col] = __halves2half2(h10, h11);
            __half q00 = __float2half_rn(v00 - __half2float(h00));
            __half q01 = __float2half_rn(v01 - __half2float(h01));
            __half q10 = __float2half_rn(v10 - __half2float(h10));
            __half q11 = __float2half_rn(v11 - __half2float(h11));
            *(__half2*)&Ol[(size_t)gr0 * DMODEL + col] = __halves2half2(q00, q01);
            *(__half2*)&Ol[(size_t)gr1 * DMODEL + col] = __halves2half2(q10, q11);
        }
    }
}

// ---------------------------------------------------------------------------
extern "C" void kernel_launch(void* const* d_in, const int* in_sizes, int n_in,
                              void* d_out, int out_size)
{
    const float* x  = (const float*)d_in[0];
    const float* Wq = (const float*)d_in[1];
    const float* bq = (const float*)d_in[2];
    const float* Wk = (const float*)d_in[3];
    const float* Wv = (const float*)d_in[4];
    const float* bv = (const float*)d_in[5];
    const float* Wo = (const float*)d_in[6];
    float* out = (float*)d_out;

    __half *xh, *xl, *wqh, *wql, *wkh, *wkl, *wvh, *wvl, *woh, *wol;
    __half *qh, *ql, *kh, *kl, *vh, *vt, *oh, *ol;
    cudaGetSymbolAddress((void**)&xh, g_xh);   cudaGetSymbolAddress((void**)&xl, g_xl);
    cudaGetSymbolAddress((void**)&wqh, g_wqh); cudaGetSymbolAddress((void**)&wql, g_wql);
    cudaGetSymbolAddress((void**)&wkh, g_wkh); cudaGetSymbolAddress((void**)&wkl, g_wkl);
    cudaGetSymbolAddress((void**)&wvh, g_wvh); cudaGetSymbolAddress((void**)&wvl, g_wvl);
    cudaGetSymbolAddress((void**)&woh, g_woh); cudaGetSymbolAddress((void**)&wol, g_wol);
    cudaGetSymbolAddress((void**)&qh, g_qh);   cudaGetSymbolAddress((void**)&ql, g_ql);
    cudaGetSymbolAddress((void**)&kh, g_kh);   cudaGetSymbolAddress((void**)&kl, g_kl);
    cudaGetSymbolAddress((void**)&vh, g_vh);   cudaGetSymbolAddress((void**)&vt, g_vt);
    cudaGetSymbolAddress((void**)&oh, g_oh);   cudaGetSymbolAddress((void**)&ol, g_ol);

    const int NX = SLEN * DMODEL;      // 4M
    const int NW = DMODEL * DMODEL;    // 1M
    split_f32<<<NX / 1024, 256>>>(x,  xh,  xl,  NX);
    split_f32<<<NW / 1024, 256>>>(Wq, wqh, wql, NW);
    split_f32<<<NW / 1024, 256>>>(Wk, wkh, wkl, NW);
    split_f32<<<NW / 1024, 256>>>(Wv, wvh, wvl, NW);
    split_f32<<<NW / 1024, 256>>>(Wo, woh, wol, NW);

    dim3 ggrid(DMODEL / BN, SLEN / BM);   // (8, 32)
    gemm_f16x3_hh<<<ggrid, 256>>>(xh, xl, wqh, wql, bq,
                                  nullptr, qh, ql, SLEN, DMODEL, DMODEL);
    gemm_f16x3_hh<<<ggrid, 256>>>(xh, xl, wkh, wkl, nullptr,
                                  nullptr, kh, kl, SLEN, DMODEL, DMODEL);
    gemm_f16x3_hh<<<ggrid, 256>>>(xh, xl, wvh, wvl, bv,
                                  nullptr, vh, nullptr, SLEN, DMODEL, DMODEL);

    dim3 tgrid(DMODEL / 32, SLEN / 32);   // (32, 128)
    transpose_h<<<tgrid, 256>>>(vh, vt);

    dim3 agrid(NQT / 2, NHEAD);           // (32, 16) balanced pairs
    flash_attn_f16<<<agrid, ATHREADS>>>(qh, ql, kh, kl, vt, oh, ol);

    gemm_f16x3_hh<<<ggrid, 256>>>(oh, ol, woh, wol, nullptr,
                                  out, nullptr, nullptr, SLEN, DMODEL, DMODEL);
}

// round 14
// speedup vs baseline: 1.1414x; 1.0468x over previous
#include <cuda_runtime.h>
#include <cuda_fp16.h>
#include <math.h>
#include <stdint.h>

#define SLEN 4096
#define DMODEL 1024
#define NHEAD 16
#define HDIM 64

// ---------------------------------------------------------------------------
// scratch (allocation-free rule: __device__ globals)
// ---------------------------------------------------------------------------
__device__ __half g_xh[SLEN * DMODEL], g_xl[SLEN * DMODEL];
__device__ __half g_wqh[DMODEL * DMODEL], g_wql[DMODEL * DMODEL];
__device__ __half g_wkh[DMODEL * DMODEL], g_wkl[DMODEL * DMODEL];
__device__ __half g_wvh[DMODEL * DMODEL], g_wvl[DMODEL * DMODEL];
__device__ __half g_woh[DMODEL * DMODEL], g_wol[DMODEL * DMODEL];
__device__ __half g_qh[SLEN * DMODEL], g_ql[SLEN * DMODEL];
__device__ __half g_kh[SLEN * DMODEL], g_kl[SLEN * DMODEL];
__device__ __half g_vh[SLEN * DMODEL];
__device__ __half g_vt[DMODEL * SLEN];           // V transposed [d][s]
__device__ __half g_oh[SLEN * DMODEL], g_ol[SLEN * DMODEL];

// ---------------------------------------------------------------------------
// helpers
// ---------------------------------------------------------------------------
__device__ __forceinline__ void mma_f16(
    float c[4], uint32_t a0, uint32_t a1, uint32_t a2, uint32_t a3,
    uint32_t b0, uint32_t b1)
{
    asm volatile(
        "mma.sync.aligned.m16n8k16.row.col.f32.f16.f16.f32 "
        "{%0,%1,%2,%3},{%4,%5,%6,%7},{%8,%9},{%0,%1,%2,%3};\n"
        : "+f"(c[0]), "+f"(c[1]), "+f"(c[2]), "+f"(c[3])
        : "r"(a0), "r"(a1), "r"(a2), "r"(a3), "r"(b0), "r"(b1));
}

__device__ __forceinline__ void cp_async16(uint32_t smem_addr, const void* gptr) {
    asm volatile("cp.async.ca.shared.global [%0], [%1], 16;\n"
                 :: "r"(smem_addr), "l"(gptr));
}
__device__ __forceinline__ void cp_commit() {
    asm volatile("cp.async.commit_group;\n" ::: "memory");
}
__device__ __forceinline__ void cp_wait0() {
    asm volatile("cp.async.wait_group 0;\n" ::: "memory");
}

// ---------------------------------------------------------------------------
// pre-pass: split fp32 array into hi/lo fp16 arrays (n % 4 == 0)
// ---------------------------------------------------------------------------
__global__ __launch_bounds__(256) void split_f32(
    const float* __restrict__ src, __half* __restrict__ hi,
    __half* __restrict__ lo, int n)
{
    int i = (blockIdx.x * 256 + threadIdx.x) * 4;
    if (i >= n) return;
    float4 v = *(const float4*)(src + i);
    __half h0 = __float2half_rn(v.x), h1 = __float2half_rn(v.y);
    __half h2 = __float2half_rn(v.z), h3 = __float2half_rn(v.w);
    __half l0 = __float2half_rn(v.x - __half2float(h0));
    __half l1 = __float2half_rn(v.y - __half2float(h1));
    __half l2 = __float2half_rn(v.z - __half2float(h2));
    __half l3 = __float2half_rn(v.w - __half2float(h3));
    __half2 ha = __halves2half2(h0, h1), hb = __halves2half2(h2, h3);
    __half2 la = __halves2half2(l0, l1), lb = __halves2half2(l2, l3);
    uint2 hp = make_uint2(*(uint32_t*)&ha, *(uint32_t*)&hb);
    uint2 lp = make_uint2(*(uint32_t*)&la, *(uint32_t*)&lb);
    *(uint2*)(hi + i) = hp;
    *(uint2*)(lo + i) = lp;
}

// ---------------------------------------------------------------------------
// transpose half [SLEN][DMODEL] -> [DMODEL][SLEN]
// ---------------------------------------------------------------------------
__global__ __launch_bounds__(256) void transpose_h(
    const __half* __restrict__ src, __half* __restrict__ dst)
{
    __shared__ __half tile[32][33];
    const int d0 = blockIdx.x * 32, s0 = blockIdx.y * 32;
    const int tx = threadIdx.x & 31, ty = threadIdx.x >> 5;   // 32 x 8
#pragma unroll
    for (int k = 0; k < 4; k++)
        tile[ty + 8 * k][tx] = src[(size_t)(s0 + ty + 8 * k) * DMODEL + d0 + tx];
    __syncthreads();
#pragma unroll
    for (int k = 0; k < 4; k++)
        dst[(size_t)(d0 + ty + 8 * k) * SLEN + s0 + tx] = tile[tx][ty + 8 * k];
}

// ---------------------------------------------------------------------------
// C[M][N] = A[M][K] @ B[N][K]^T + bias[N] via 3xFP16 mma (pre-split inputs).
// ---------------------------------------------------------------------------
#define BM 128
#define BN 128
#define GS 12

__global__ __launch_bounds__(256) void gemm_f16x3_hh(
    const __half* __restrict__ Ah, const __half* __restrict__ Al,
    const __half* __restrict__ Bh, const __half* __restrict__ Bl,
    const float* __restrict__ bias,
    float* __restrict__ Cf, __half* __restrict__ Ch, __half* __restrict__ Cl,
    int M, int N, int K)
{
    __shared__ uint32_t AsH[2][BM][GS];
    __shared__ uint32_t AsL[2][BM][GS];
    __shared__ uint32_t BsH[2][BN][GS];
    __shared__ uint32_t BsL[2][BN][GS];

    const int tid  = threadIdx.x;
    const int warp = tid >> 5;
    const int lane = tid & 31;
    const int wm = warp >> 2;
    const int wn = warp & 3;
    const int lr = lane >> 2;
    const int qd = lane & 3;
    const int brow = blockIdx.y * BM;
    const int bcol = blockIdx.x * BN;

    float acc[4][4][4];
#pragma unroll
    for (int i = 0; i < 4; i++)
#pragma unroll
        for (int j = 0; j < 4; j++)
#pragma unroll
            for (int f = 0; f < 4; f++) acc[i][j][f] = 0.f;

    const int NKB = K / 16;
    const int lrow = tid >> 1;
    const int lpart = tid & 1;

    auto load_tile = [&](int kb, int buf) {
        size_t ga = (size_t)(brow + lrow) * K + kb * 16 + lpart * 8;
        size_t gb = (size_t)(bcol + lrow) * K + kb * 16 + lpart * 8;
        cp_async16((uint32_t)__cvta_generic_to_shared(&AsH[buf][lrow][lpart * 4]), &Ah[ga]);
        cp_async16((uint32_t)__cvta_generic_to_shared(&AsL[buf][lrow][lpart * 4]), &Al[ga]);
        cp_async16((uint32_t)__cvta_generic_to_shared(&BsH[buf][lrow][lpart * 4]), &Bh[gb]);
        cp_async16((uint32_t)__cvta_generic_to_shared(&BsL[buf][lrow][lpart * 4]), &Bl[gb]);
        cp_commit();
    };

    load_tile(0, 0);
    cp_wait0();
    __syncthreads();

    for (int kb = 0; kb < NKB; kb++) {
        const int buf = kb & 1;
        if (kb + 1 < NKB) load_tile(kb + 1, buf ^ 1);

        uint32_t ah[4][4], al[4][4];
#pragma unroll
        for (int mt = 0; mt < 4; mt++) {
            int r = wm * 64 + mt * 16 + lr;
            ah[mt][0] = AsH[buf][r    ][qd];
            ah[mt][1] = AsH[buf][r + 8][qd];
            ah[mt][2] = AsH[buf][r    ][qd + 4];
            ah[mt][3] = AsH[buf][r + 8][qd + 4];
            al[mt][0] = AsL[buf][r    ][qd];
            al[mt][1] = AsL[buf][r + 8][qd];
            al[mt][2] = AsL[buf][r    ][qd + 4];
            al[mt][3] = AsL[buf][r + 8][qd + 4];
        }
#pragma unroll
        for (int nt = 0; nt < 4; nt++) {
            int c = wn * 32 + nt * 8 + lr;
            uint32_t bh0 = BsH[buf][c][qd], bh1 = BsH[buf][c][qd + 4];
            uint32_t bl0 = BsL[buf][c][qd], bl1 = BsL[buf][c][qd + 4];
#pragma unroll
            for (int mt = 0; mt < 4; mt++) {
                mma_f16(acc[mt][nt], ah[mt][0], ah[mt][1], ah[mt][2], ah[mt][3], bh0, bh1);
                mma_f16(acc[mt][nt], ah[mt][0], ah[mt][1], ah[mt][2], ah[mt][3], bl0, bl1);
                mma_f16(acc[mt][nt], al[mt][0], al[mt][1], al[mt][2], al[mt][3], bh0, bh1);
            }
        }
        cp_wait0();
        __syncthreads();
    }

#pragma unroll
    for (int mt = 0; mt < 4; mt++) {
        int r0 = brow + wm * 64 + mt * 16 + lr;
#pragma unroll
        for (int nt = 0; nt < 4; nt++) {
            int col = bcol + wn * 32 + nt * 8 + 2 * qd;
            float b0 = bias ? bias[col]     : 0.f;
            float b1 = bias ? bias[col + 1] : 0.f;
            float v00 = acc[mt][nt][0] + b0, v01 = acc[mt][nt][1] + b1;
            float v10 = acc[mt][nt][2] + b0, v11 = acc[mt][nt][3] + b1;
            if (Cf) {
                *(float2*)&Cf[(size_t)r0 * N + col]       = make_float2(v00, v01);
                *(float2*)&Cf[(size_t)(r0 + 8) * N + col] = make_float2(v10, v11);
            } else {
                __half h00 = __float2half_rn(v00), h01 = __float2half_rn(v01);
                __half h10 = __float2half_rn(v10), h11 = __float2half_rn(v11);
                *(__half2*)&Ch[(size_t)r0 * N + col]       = __halves2half2(h00, h01);
                *(__half2*)&Ch[(size_t)(r0 + 8) * N + col] = __halves2half2(h10, h11);
                if (Cl) {
                    __half q00 = __float2half_rn(v00 - __half2float(h00));
                    __half q01 = __float2half_rn(v01 - __half2float(h01));
                    __half q10 = __float2half_rn(v10 - __half2float(h10));
                    __half q11 = __float2half_rn(v11 - __half2float(h11));
                    *(__half2*)&Cl[(size_t)r0 * N + col]       = __halves2half2(q00, q01);
                    *(__half2*)&Cl[(size_t)(r0 + 8) * N + col] = __halves2half2(q10, q11);
                }
            }
        }
    }
}

// ---------------------------------------------------------------------------
// Tensor-core causal flash attention with ALiBi (all-fp16 mma).
// BT=64: half the softmax/barrier episodes per unit work. Dynamic smem 54KB.
// BQ=64 = 4 warps x m16, 128 threads, balanced q-tile pairs, 4 CTAs/SM.
// ---------------------------------------------------------------------------
#define BQ 64
#define BT 64
#define QS 36
#define VROW 72        // halves per VsT row (64 data + 8 pad; 16B-mult offsets)
#define ATHREADS 128
#define NQT (SLEN / BQ)       // 64

#define KH_BYTES (2 * BT * QS * 4)        // 18432
#define KL_BYTES (2 * BT * QS * 4)        // 18432
#define VT_BYTES (2 * HDIM * VROW * 2)    // 18432
#define ASMEM (KH_BYTES + KL_BYTES + VT_BYTES)   // 55296

__global__ __launch_bounds__(ATHREADS, 4) void flash_attn_f16(
    const __half* __restrict__ Qh, const __half* __restrict__ Ql,
    const __half* __restrict__ Kh, const __half* __restrict__ Kl,
    const __half* __restrict__ Vt,
    __half* __restrict__ Oh, __half* __restrict__ Ol)
{
    extern __shared__ char dyn[];
    uint32_t (*Kh2)[BT][QS]  = (uint32_t(*)[BT][QS])(dyn);
    uint32_t (*Kl2)[BT][QS]  = (uint32_t(*)[BT][QS])(dyn + KH_BYTES);
    __half   (*VsT)[HDIM][VROW] = (__half(*)[HDIM][VROW])(dyn + KH_BYTES + KL_BYTES);

    const int h = blockIdx.y;

    const int tid  = threadIdx.x;
    const int warp = tid >> 5;
    const int lane = tid & 31;
    const int lr   = lane >> 2;
    const int qd   = lane & 3;
    const int R    = warp * 16;
    const int hd   = h * HDIM;

    const float LOG2E = 1.4426950408889634f;
    const float sc2 = 0.125f * LOG2E;
    const float sl2 = exp2f(-0.5f * (float)(h + 1)) * LOG2E;

    auto load_kv = [&](int t, int buf) {
        const int t0 = t * BT;
        // K hi/lo: 64 rows x 128B = 8 chunks/row -> 512 chunks, 4 iters
#pragma unroll
        for (int it = 0; it < 4; it++) {
            int f = tid + it * ATHREADS;        // 0..511
            int r = f >> 3, part = f & 7;
            size_t g = (size_t)(t0 + r) * DMODEL + hd + part * 8;
            cp_async16((uint32_t)__cvta_generic_to_shared(&Kh2[buf][r][part * 4]), &Kh[g]);
            cp_async16((uint32_t)__cvta_generic_to_shared(&Kl2[buf][r][part * 4]), &Kl[g]);
        }
        // V^T: 64 rows x 128B = 8 chunks/row -> 512 chunks, 4 iters
#pragma unroll
        for (int it = 0; it < 4; it++) {
            int f = tid + it * ATHREADS;
            int d = f >> 3, c = f & 7;
            size_t g = (size_t)(hd + d) * SLEN + t0 + c * 8;
            cp_async16((uint32_t)__cvta_generic_to_shared(&VsT[buf][d][c * 8]), &Vt[g]);
        }
        cp_commit();
    };

#pragma unroll 1
    for (int rep = 0; rep < 2; rep++) {
        const int qt = (rep == 0) ? (int)blockIdx.x : (NQT - 1 - (int)blockIdx.x);
        const int q0 = qt * BQ;

        const int gr0 = q0 + R + lr;
        const int gr1 = gr0 + 8;

        load_kv(0, 0);

        // ---- Q fragments (hi and lo) straight from gmem ----
        uint32_t qh[4][4], ql[4][4];
#pragma unroll
        for (int kt = 0; kt < 4; kt++) {
            int c0 = kt * 8 + qd;
            size_t b0 = (size_t)gr0 * DMODEL + hd + 2 * c0;
            size_t b1 = (size_t)gr1 * DMODEL + hd + 2 * c0;
            qh[kt][0] = *(const uint32_t*)&Qh[b0];
            qh[kt][1] = *(const uint32_t*)&Qh[b1];
            qh[kt][2] = *(const uint32_t*)&Qh[b0 + 8];
            qh[kt][3] = *(const uint32_t*)&Qh[b1 + 8];
            ql[kt][0] = *(const uint32_t*)&Ql[b0];
            ql[kt][1] = *(const uint32_t*)&Ql[b1];
            ql[kt][2] = *(const uint32_t*)&Ql[b0 + 8];
            ql[kt][3] = *(const uint32_t*)&Ql[b1 + 8];
        }

        cp_wait0();
        __syncthreads();

        float oacc[8][4];
#pragma unroll
        for (int i = 0; i < 8; i++)
#pragma unroll
            for (int j = 0; j < 4; j++) oacc[i][j] = 0.f;
        float m0 = -INFINITY, m1 = -INFINITY, l0 = 0.f, l1 = 0.f;

        const int ntiles = qt + 1;
        for (int t = 0; t < ntiles; t++) {
            const int buf = t & 1;
            const int t0 = t * BT;
            if (t + 1 < ntiles) load_kv(t + 1, buf ^ 1);

            // ---- S = Q K^T (3xFP16, k16), 8 n-tiles ----
            float sa[8][4];
#pragma unroll
            for (int nt = 0; nt < 8; nt++)
#pragma unroll
                for (int f = 0; f < 4; f++) sa[nt][f] = 0.f;

#pragma unroll
            for (int kt = 0; kt < 4; kt++) {
                int c0 = kt * 8 + qd;
#pragma unroll
                for (int nt = 0; nt < 8; nt++) {
                    int tr_ = nt * 8 + lr;
                    uint32_t bh0 = Kh2[buf][tr_][c0], bh1 = Kh2[buf][tr_][c0 + 4];
                    uint32_t bl0 = Kl2[buf][tr_][c0], bl1 = Kl2[buf][tr_][c0 + 4];
                    mma_f16(sa[nt], qh[kt][0], qh[kt][1], qh[kt][2], qh[kt][3], bh0, bh1);
                    mma_f16(sa[nt], qh[kt][0], qh[kt][1], qh[kt][2], qh[kt][3], bl0, bl1);
                    mma_f16(sa[nt], ql[kt][0], ql[kt][1], ql[kt][2], ql[kt][3], bh0, bh1);
                }
            }

            // ---- bias + causal mask + online softmax (base-2) ----
            float mx0 = -INFINITY, mx1 = -INFINITY;
#pragma unroll
            for (int nt = 0; nt < 8; nt++) {
                int c = t0 + nt * 8 + 2 * qd;
                float x00 = sa[nt][0] * sc2 - sl2 * (float)c;
                float x01 = sa[nt][1] * sc2 - sl2 * (float)(c + 1);
                float x10 = sa[nt][2] * sc2 - sl2 * (float)c;
                float x11 = sa[nt][3] * sc2 - sl2 * (float)(c + 1);
                if (c     > gr0) x00 = -INFINITY;
                if (c + 1 > gr0) x01 = -INFINITY;
                if (c     > gr1) x10 = -INFINITY;
                if (c + 1 > gr1) x11 = -INFINITY;
                sa[nt][0] = x00; sa[nt][1] = x01; sa[nt][2] = x10; sa[nt][3] = x11;
                mx0 = fmaxf(mx0, fmaxf(x00, x01));
                mx1 = fmaxf(mx1, fmaxf(x10, x11));
            }
            mx0 = fmaxf(mx0, __shfl_xor_sync(0xffffffffu, mx0, 1));
            mx0 = fmaxf(mx0, __shfl_xor_sync(0xffffffffu, mx0, 2));
            mx1 = fmaxf(mx1, __shfl_xor_sync(0xffffffffu, mx1, 1));
            mx1 = fmaxf(mx1, __shfl_xor_sync(0xffffffffu, mx1, 2));

            float nm0 = fmaxf(m0, mx0), nm1 = fmaxf(m1, mx1);
            float s0 = exp2f(m0 - nm0), s1 = exp2f(m1 - nm1);
            m0 = nm0; m1 = nm1;

            float rs0 = 0.f, rs1 = 0.f;
            uint32_t pa[4][4];
#pragma unroll
            for (int nt = 0; nt < 8; nt++) {
                float p00 = exp2f(sa[nt][0] - m0);
                float p01 = exp2f(sa[nt][1] - m0);
                float p10 = exp2f(sa[nt][2] - m1);
                float p11 = exp2f(sa[nt][3] - m1);
                rs0 += p00 + p01;
                rs1 += p10 + p11;
                __half2 h0 = __floats2half2_rn(p00, p01);
                __half2 h1 = __floats2half2_rn(p10, p11);
                pa[nt >> 1][(nt & 1) * 2 + 0] = *(uint32_t*)&h0;
                pa[nt >> 1][(nt & 1) * 2 + 1] = *(uint32_t*)&h1;
            }
            rs0 += __shfl_xor_sync(0xffffffffu, rs0, 1);
            rs0 += __shfl_xor_sync(0xffffffffu, rs0, 2);
            rs1 += __shfl_xor_sync(0xffffffffu, rs1, 1);
            rs1 += __shfl_xor_sync(0xffffffffu, rs1, 2);
            l0 = l0 * s0 + rs0;
            l1 = l1 * s1 + rs1;

            // ---- rescale O, then O += P V (fp16 mma, 4 k-chunks) ----
#pragma unroll
            for (int ntO = 0; ntO < 8; ntO++) {
                oacc[ntO][0] *= s0; oacc[ntO][1] *= s0;
                oacc[ntO][2] *= s1; oacc[ntO][3] *= s1;
            }
#pragma unroll
            for (int ktp = 0; ktp < 4; ktp++) {
#pragma unroll
                for (int ntO = 0; ntO < 8; ntO++) {
                    int dcol = ntO * 8 + lr;
                    uint32_t b0 = *(const uint32_t*)&VsT[buf][dcol][ktp * 16 + 2 * qd];
                    uint32_t b1 = *(const uint32_t*)&VsT[buf][dcol][ktp * 16 + 2 * qd + 8];
                    mma_f16(oacc[ntO], pa[ktp][0], pa[ktp][1], pa[ktp][2], pa[ktp][3], b0, b1);
                }
            }
            cp_wait0();
            __syncthreads();
        }

        // ---- epilogue: write hi/lo halves for the output GEMM ----
        float inv0 = 1.f / l0, inv1 = 1.f / l1;
#pragma unroll
        for (int ntO = 0; ntO < 8; ntO++) {
            int col = hd + ntO * 8 + 2 * qd;
            float v00 = oacc[ntO][0] * inv0, v01 = oacc[ntO][1] * inv0;
            float v10 = oacc[ntO][2] * inv1, v11 = oacc[ntO][3] * inv1;
            __half h00 = __float2half_rn(v00), h01 = __float2half_rn(v01);
            __half h10 = __float2half_rn(v10), h11 = __float2half_rn(v11);
            *(__half2*)&Oh[(size_t)gr0 * DMODEL + col] = __halves2half2(h00, h01);
            *(__half2*)&Oh[(size_t)gr1 * DMODEL + col] = __halves2half2(h10, h11);
            __half q00 = __float2half_rn(v00 - __half2float(h00));
            __half q01 = __float2half_rn(v01 - __half2float(h01));
            __half q10 = __float2half_rn(v10 - __half2float(h10));
            __half q11 = __float2half_rn(v11 - __half2float(h11));
            *(__half2*)&Ol[(size_t)gr0 * DMODEL + col] = __halves2half2(q00, q01);
            *(__half2*)&Ol[(size_t)gr1 * DMODEL + col] = __halves2half2(q10, q11);
        }
    }
}

// ---------------------------------------------------------------------------
extern "C" void kernel_launch(void* const* d_in, const int* in_sizes, int n_in,
                              void* d_out, int out_size)
{
    const float* x  = (const float*)d_in[0];
    const float* Wq = (const float*)d_in[1];
    const float* bq = (const float*)d_in[2];
    const float* Wk = (const float*)d_in[3];
    const float* Wv = (const float*)d_in[4];
    const float* bv = (const float*)d_in[5];
    const float* Wo = (const float*)d_in[6];
    float* out = (float*)d_out;

    __half *xh, *xl, *wqh, *wql, *wkh, *wkl, *wvh, *wvl, *woh, *wol;
    __half *qh, *ql, *kh, *kl, *vh, *vt, *oh, *ol;
    cudaGetSymbolAddress((void**)&xh, g_xh);   cudaGetSymbolAddress((void**)&xl, g_xl);
    cudaGetSymbolAddress((void**)&wqh, g_wqh); cudaGetSymbolAddress((void**)&wql, g_wql);
    cudaGetSymbolAddress((void**)&wkh, g_wkh); cudaGetSymbolAddress((void**)&wkl, g_wkl);
    cudaGetSymbolAddress((void**)&wvh, g_wvh); cudaGetSymbolAddress((void**)&wvl, g_wvl);
    cudaGetSymbolAddress((void**)&woh, g_woh); cudaGetSymbolAddress((void**)&wol, g_wol);
    cudaGetSymbolAddress((void**)&qh, g_qh);   cudaGetSymbolAddress((void**)&ql, g_ql);
    cudaGetSymbolAddress((void**)&kh, g_kh);   cudaGetSymbolAddress((void**)&kl, g_kl);
    cudaGetSymbolAddress((void**)&vh, g_vh);   cudaGetSymbolAddress((void**)&vt, g_vt);
    cudaGetSymbolAddress((void**)&oh, g_oh);   cudaGetSymbolAddress((void**)&ol, g_ol);

    static int smem_set = 0;
    if (!smem_set) {
        cudaFuncSetAttribute(flash_attn_f16,
                             cudaFuncAttributeMaxDynamicSharedMemorySize, ASMEM);
        smem_set = 1;
    }

    const int NX = SLEN * DMODEL;      // 4M
    const int NW = DMODEL * DMODEL;    // 1M
    split_f32<<<NX / 1024, 256>>>(x,  xh,  xl,  NX);
    split_f32<<<NW / 1024, 256>>>(Wq, wqh, wql, NW);
    split_f32<<<NW / 1024, 256>>>(Wk, wkh, wkl, NW);
    split_f32<<<NW / 1024, 256>>>(Wv, wvh, wvl, NW);
    split_f32<<<NW / 1024, 256>>>(Wo, woh, wol, NW);

    dim3 ggrid(DMODEL / BN, SLEN / BM);   // (8, 32)
    gemm_f16x3_hh<<<ggrid, 256>>>(xh, xl, wqh, wql, bq,
                                  nullptr, qh, ql, SLEN, DMODEL, DMODEL);
    gemm_f16x3_hh<<<ggrid, 256>>>(xh, xl, wkh, wkl, nullptr,
                                  nullptr, kh, kl, SLEN, DMODEL, DMODEL);
    gemm_f16x3_hh<<<ggrid, 256>>>(xh, xl, wvh, wvl, bv,
                                  nullptr, vh, nullptr, SLEN, DMODEL, DMODEL);

    dim3 tgrid(DMODEL / 32, SLEN / 32);   // (32, 128)
    transpose_h<<<tgrid, 256>>>(vh, vt);

    dim3 agrid(NQT / 2, NHEAD);           // (32, 16) balanced pairs
    flash_attn_f16<<<agrid, ATHREADS, ASMEM>>>(qh, ql, kh, kl, vt, oh, ol);

    gemm_f16x3_hh<<<ggrid, 256>>>(oh, ol, woh, wol, nullptr,
                                  out, nullptr, nullptr, SLEN, DMODEL, DMODEL);
}